// round 7
// baseline (speedup 1.0000x reference)
#include <cuda_runtime.h>
#include <math.h>

#define NB 16
#define HW 512
#define NPIX (NB*HW*HW)
#define LCAP 768
#define K4CTAS (NB*LCAP/32)   // 384

// ---------------- device scratch ----------------
__device__ float    g_bval[NB*4096];
__device__ int      g_bpos[NB*4096];
__device__ int      g_list[NB*LCAP];
__device__ int      g_cnt[NB];
__device__ double   g_pb[4096];
__device__ double   g_pr[4096];
__device__ double   g_pc[K4CTAS];
__device__ unsigned g_arrive;

__device__ __forceinline__ int refl512(int i){ return i<0 ? -i : (i>511 ? 1022-i : i); }
__device__ __forceinline__ int clamp512(int i){ return i<0?0:(i>511?511:i); }

__device__ __forceinline__ void gw7(float* w){
  float e0=expf(-4.5f), e1=expf(-2.0f), e2=expf(-0.5f);
  float s=1.0f+2.0f*(e0+e1+e2);
  w[0]=e0/s; w[1]=e1/s; w[2]=e2/s; w[3]=1.0f/s; w[4]=w[2]; w[5]=w[1]; w[6]=w[0];
}

// smem layout (floats)
#define OFF_P01 0       // 42 rows x 44 float2 -> 3696 floats
#define OFF_P2  3696    // 42 x 44 floats      -> 1848
#define OFF_T01 5544    // 42 rows x 36 float2 -> 3024
#define OFF_T2  8568    // 42 x 36 floats      -> 1512
#define OFF_SG  10080   // 44 rows x 48 floats -> 2112 (cols 0..45 valid)
#define OFF_RB  12192   // 32
#define OFF_RR  12224   // 32
#define BUFSZ   12256   // 49024 B

// ============ KMAIN ============
__global__ __launch_bounds__(1024) void kmain(const float* __restrict__ imgs,
                                              const float* __restrict__ scores){
  const int b = blockIdx.z;
  const int ty0 = blockIdx.y*32, tx0 = blockIdx.x*32;
  __shared__ __align__(16) float buf[BUFSZ];
  float* p01 = buf + OFF_P01;
  float* p2  = buf + OFF_P2;
  float* t01 = buf + OFF_T01;
  float* t2  = buf + OFF_T2;
  float* sg  = buf + OFF_SG;
  float* resp= buf + OFF_SG;   // aliases sg (dead after B); 36x36
  float* rm  = buf;            // aliases p01 (dead after C); 36x32
  float* sv  = buf + 1152;     // 32x32
  float* sc  = buf;            // phase0: 36x36
  float* rs  = buf + 1296;     // phase0: 36x32
  float* rb  = buf + OFF_RB;
  float* rr2 = buf + OFF_RR;

  const int ty = threadIdx.y, tx = threadIdx.x;
  const int tid = ty*32 + tx;
  const float NEG = __int_as_float(0xff800000u);
  const bool interior = (blockIdx.x-1u < 14u) && (blockIdx.y-1u < 14u);

  const float* rrp = imgs + (size_t)b*3*HW*HW;
  const float* ggp = rrp + HW*HW;
  const float* bbp = ggp + HW*HW;
  const float* sp  = scores + (size_t)b*HW*HW;

  // ---- load scores tile (36x36) and gray tile (44x46) back-to-back, one barrier ----
  for (int iy=ty; iy<36; iy+=32)
    for (int ix=tx; ix<36; ix+=32)
      sc[iy*36+ix] = sp[refl512(ty0-2+iy)*HW + refl512(tx0-2+ix)];
  for (int iy=ty; iy<44; iy+=32)
    for (int ix=tx; ix<46; ix+=32){
      int gy=clamp512(ty0-6+iy), gx=clamp512(tx0-6+ix);
      int o=gy*HW+gx;
      sg[iy*48+ix] = 0.299f*rrp[o] + 0.587f*ggp[o] + 0.114f*bbp[o];
    }
  __syncthreads();

  // ---- phase0a: row sums of 5 (scores), strips of 4 ----
  if (tid < 288){
    int iy = tid>>3, x0 = (tid&7)*4;
    int bidx = iy*36 + x0;
    float4 u  = *(const float4*)&sc[bidx];
    float4 u2 = *(const float4*)&sc[bidx+4];
    float v8 = sc[bidx+8];
    float v[9] = {u.x,u.y,u.z,u.w,u2.x,u2.y,u2.z,u2.w,v8};
    float s2[6];
    #pragma unroll
    for (int i=0;i<6;i++) s2[i]=v[i]+v[i+1];
    float4 o;
    o.x = s2[0]+s2[2]+v[4];
    o.y = s2[1]+s2[3]+v[5];
    o.z = s2[2]+s2[4]+v[6];
    o.w = s2[3]+s2[5]+v[7];
    *(float4*)&rs[iy*32+x0] = o;
  }
  __syncthreads();

  // ---- phase0b: laplacian + reg + base bce; 512 threads x 2 outputs ----
  {
    float v1=0.f, v2=0.f;
    if (tid < 512){
      int oy = tid>>4, x0 = (tid&15)*2;
      float S0=0.f, S1=0.f;
      #pragma unroll
      for (int k=0;k<5;k++){
        float2 u = *(const float2*)&rs[(oy+k)*32+x0];
        S0 += u.x; S1 += u.y;
      }
      float2 pc = *(const float2*)&sc[(oy+2)*36 + x0+2];
      float lap0 = (S0 - 25.0f*pc.x)*(1.0f/48.0f);
      float lap1 = (S1 - 25.0f*pc.y)*(1.0f/48.0f);
      v2 = pc.x*expf(-lap0) + pc.y*expf(-lap1);
      v1 = -fmaxf(log1pf(-pc.x),-100.0f) - fmaxf(log1pf(-pc.y),-100.0f);
    }
    #pragma unroll
    for (int off=16;off;off>>=1){
      v1 += __shfl_down_sync(0xffffffffu, v1, off);
      v2 += __shfl_down_sync(0xffffffffu, v2, off);
    }
    if ((tid&31)==0){ rb[tid>>5]=v1; rr2[tid>>5]=v2; }
  }
  __syncthreads();
  if (tid<32){
    float a1=rb[tid], a2=rr2[tid];
    #pragma unroll
    for (int off=16;off;off>>=1){
      a1 += __shfl_down_sync(0xffffffffu, a1, off);
      a2 += __shfl_down_sync(0xffffffffu, a2, off);
    }
    if (tid==0){
      int bid = (blockIdx.z*16 + blockIdx.y)*16 + blockIdx.x;
      g_pb[bid]=(double)a1; g_pr[bid]=(double)a2;
    }
  }
  __syncthreads();   // protects sc/rs before B overwrites; rb read done

  // ---- B: gradient products, 42 rows x 11 strips of 4 (cols 0..43 incl pad) ----
  if (tid < 462){
    int iy = tid/11;
    int ix0 = (tid - iy*11)*4;
    float dxv[4], dyv[4];
    if (interior){
      int r0 = iy*48 + ix0;
      float4 a; float2 bq;
      float g0[6], g1[6], g2[6];
      a=*(const float4*)&sg[r0];      bq=*(const float2*)&sg[r0+4];
      g0[0]=a.x;g0[1]=a.y;g0[2]=a.z;g0[3]=a.w;g0[4]=bq.x;g0[5]=bq.y;
      a=*(const float4*)&sg[r0+48];   bq=*(const float2*)&sg[r0+52];
      g1[0]=a.x;g1[1]=a.y;g1[2]=a.z;g1[3]=a.w;g1[4]=bq.x;g1[5]=bq.y;
      a=*(const float4*)&sg[r0+96];   bq=*(const float2*)&sg[r0+100];
      g2[0]=a.x;g2[1]=a.y;g2[2]=a.z;g2[3]=a.w;g2[4]=bq.x;g2[5]=bq.y;
      #pragma unroll
      for (int c=0;c<4;c++){
        dxv[c]=(g0[c+2]-g0[c] + 2.0f*(g1[c+2]-g1[c]) + g2[c+2]-g2[c])*0.125f;
        dyv[c]=(g2[c]-g0[c] + 2.0f*(g2[c+1]-g0[c+1]) + g2[c+2]-g0[c+2])*0.125f;
      }
    } else {
      int qy = refl512(ty0-5+iy);
      int ly = qy - ty0 + 6;
      #pragma unroll
      for (int c=0;c<4;c++){
        int qx = refl512(tx0-5+ix0+c);
        int lx = qx - tx0 + 6;
        float a =sg[(ly-1)*48+lx-1], b_=sg[(ly-1)*48+lx], cc=sg[(ly-1)*48+lx+1];
        float d =sg[ ly   *48+lx-1],                      e =sg[ ly   *48+lx+1];
        float f =sg[(ly+1)*48+lx-1], h =sg[(ly+1)*48+lx], kk=sg[(ly+1)*48+lx+1];
        dxv[c]=(cc-a+2.0f*(e-d)+kk-f)*0.125f;
        dyv[c]=(f-a+2.0f*(h-b_)+kk-cc)*0.125f;
      }
    }
    int ob = 2*(iy*44 + ix0);
    *(float4*)&p01[ob]   = make_float4(dxv[0]*dxv[0], dyv[0]*dyv[0], dxv[1]*dxv[1], dyv[1]*dyv[1]);
    *(float4*)&p01[ob+4] = make_float4(dxv[2]*dxv[2], dyv[2]*dyv[2], dxv[3]*dxv[3], dyv[3]*dyv[3]);
    *(float4*)&p2[iy*44 + ix0] = make_float4(dxv[0]*dyv[0], dxv[1]*dyv[1], dxv[2]*dyv[2], dxv[3]*dyv[3]);
  }
  __syncthreads();

  float w[7]; gw7(w);

  // ---- C: row blur, 42 rows x 9 strips of 4 ----
  if (tid < 378){
    int iy = tid/9;
    int x0 = (tid - iy*9)*4;
    float O0[4]={0,0,0,0}, O1[4]={0,0,0,0}, O2[4]={0,0,0,0};
    int base2 = 2*(iy*44 + x0);
    #pragma unroll
    for (int m=0;m<5;m++){
      float4 v = *(const float4*)&p01[base2 + 4*m];
      int k0 = 2*m, k1 = 2*m+1;
      #pragma unroll
      for (int c=0;c<4;c++){
        int d0 = k0-c;
        if (d0>=0 && d0<7){ O0[c]+=w[d0]*v.x; O1[c]+=w[d0]*v.y; }
        int d1 = k1-c;
        if (d1>=0 && d1<7){ O0[c]+=w[d1]*v.z; O1[c]+=w[d1]*v.w; }
      }
    }
    int baser = iy*44 + x0;
    {
      float4 v = *(const float4*)&p2[baser];
      float4 u = *(const float4*)&p2[baser+4];
      float2 t = *(const float2*)&p2[baser+8];
      float r[10]={v.x,v.y,v.z,v.w,u.x,u.y,u.z,u.w,t.x,t.y};
      #pragma unroll
      for (int c=0;c<4;c++){
        float s=0.f;
        #pragma unroll
        for (int k=0;k<7;k++) s += w[k]*r[c+k];
        O2[c]=s;
      }
    }
    int ot = 2*(iy*36 + x0);
    *(float4*)&t01[ot]   = make_float4(O0[0],O1[0],O0[1],O1[1]);
    *(float4*)&t01[ot+4] = make_float4(O0[2],O1[2],O0[3],O1[3]);
    *(float4*)&t2[iy*36 + x0] = make_float4(O2[0],O2[1],O2[2],O2[3]);
  }
  __syncthreads();

  // ---- D: col blur + min-eig; 18 x-pairs x 9 y-strips of 4 ----
  if (tid < 162){
    int yj = tid/18;
    int xp = tid - yj*18;
    int y0 = 4*yj, x0 = 2*xp;
    float A0[4]={0,0,0,0},A1[4]={0,0,0,0},A2[4]={0,0,0,0};
    float B0[4]={0,0,0,0},B1[4]={0,0,0,0},B2[4]={0,0,0,0};
    #pragma unroll
    for (int k=0;k<10;k++){
      int o = (y0+k)*36 + x0;
      float4 qq = *(const float4*)&t01[2*o];
      float2 rv = *(const float2*)&t2[o];
      #pragma unroll
      for (int j=0;j<4;j++){
        int ki = k - j;
        if (ki>=0 && ki<7){
          float wk = w[ki];
          A0[j]+=wk*qq.x; A1[j]+=wk*qq.y; A2[j]+=wk*rv.x;
          B0[j]+=wk*qq.z; B1[j]+=wk*qq.w; B2[j]+=wk*rv.y;
        }
      }
    }
    int rx = tx0-2+x0;
    bool okx0 = (rx>=0 && rx<HW), okx1 = (rx+1>=0 && rx+1<HW);
    #pragma unroll
    for (int j=0;j<4;j++){
      int ry = ty0-2+y0+j;
      bool oky = (ry>=0 && ry<HW);
      float det=A0[j]*A1[j]-A2[j]*A2[j], tr=A0[j]+A1[j];
      float r0=0.5f*(tr - sqrtf(fabsf(tr*tr-4.0f*det)));
      det=B0[j]*B1[j]-B2[j]*B2[j]; tr=B0[j]+B1[j];
      float r1=0.5f*(tr - sqrtf(fabsf(tr*tr-4.0f*det)));
      r0 = (oky && okx0) ? r0 : NEG;
      r1 = (oky && okx1) ? r1 : NEG;
      *(float2*)&resp[(y0+j)*36 + x0] = make_float2(r0,r1);
    }
  }
  __syncthreads();

  // ---- E0: row max of 5, 36 rows x 8 strips of 4 ----
  if (tid < 288){
    int iy = tid>>3, x0 = (tid&7)*4;
    int bidx = iy*36 + x0;
    float4 u  = *(const float4*)&resp[bidx];
    float4 u2 = *(const float4*)&resp[bidx+4];
    float v[8]={u.x,u.y,u.z,u.w,u2.x,u2.y,u2.z,u2.w};
    float m2[6];
    #pragma unroll
    for (int i=0;i<6;i++) m2[i]=fmaxf(v[i],v[i+1]);
    float4 o;
    o.x = fmaxf(fmaxf(m2[0],m2[2]),v[4]);
    o.y = fmaxf(fmaxf(m2[1],m2[3]),v[5]);
    o.z = fmaxf(fmaxf(m2[2],m2[4]),v[6]);
    o.w = fmaxf(fmaxf(m2[3],m2[5]),v[7]);
    *(float4*)&rm[iy*32+x0] = o;
  }
  __syncthreads();

  // ---- E1: col max of 5 -> NMS, 32 rows x 8 strips of 4 ----
  if (tid < 256){
    int oy = tid>>3, x0 = (tid&7)*4;
    float m0=NEG,m1=NEG,m2_=NEG,m3=NEG;
    #pragma unroll
    for (int k=0;k<5;k++){
      float4 u = *(const float4*)&rm[(oy+k)*32+x0];
      m0=fmaxf(m0,u.x); m1=fmaxf(m1,u.y); m2_=fmaxf(m2_,u.z); m3=fmaxf(m3,u.w);
    }
    float2 c0 = *(const float2*)&resp[(oy+2)*36 + x0+2];
    float2 c1 = *(const float2*)&resp[(oy+2)*36 + x0+4];
    float4 o;
    o.x = (c0.x==m0 ) ? c0.x : 0.0f;
    o.y = (c0.y==m1 ) ? c0.y : 0.0f;
    o.z = (c1.x==m2_) ? c1.x : 0.0f;
    o.w = (c1.y==m3 ) ? c1.y : 0.0f;
    *(float4*)&sv[oy*32+x0] = o;
  }
  __syncthreads();

  // ---- E2: per-8x8-block argmax (strict >, row-major first-wins) ----
  if ((ty&7)==0 && (tx&7)==0){
    float bv = sv[ty*32+tx];
    int   bp = (ty0+ty)*HW + (tx0+tx);
    #pragma unroll
    for (int r=0;r<8;r++){
      float4 u0 = *(const float4*)&sv[(ty+r)*32 + tx];
      float4 u1 = *(const float4*)&sv[(ty+r)*32 + tx + 4];
      float q[8]={u0.x,u0.y,u0.z,u0.w,u1.x,u1.y,u1.z,u1.w};
      #pragma unroll
      for (int j=0;j<8;j++){
        if (q[j] > bv){ bv=q[j]; bp=(ty0+ty+r)*HW + (tx0+tx+j); }
      }
    }
    int bidx = b*4096 + ((ty0+ty)>>3)*64 + ((tx0+tx)>>3);
    g_bval[bidx]=bv; g_bpos[bidx]=bp;
  }
}

// ============ K2: radix-select + select + second NMS + deterministic compaction ============
__global__ __launch_bounds__(1024) void k2(){
  const int img = blockIdx.x, tid = threadIdx.x;
  const int lane = tid&31, wid = tid>>5;
  __shared__ float fv[4096];
  __shared__ int   pos[4096];
  __shared__ unsigned hist[256];
  __shared__ int wsum[32];
  __shared__ unsigned s_prefix;
  __shared__ int s_k;
  for (int i=tid;i<4096;i+=1024){
    fv[i]=g_bval[img*4096+i];
    pos[i]=g_bpos[img*4096+i];
  }
  if (tid==0){ s_prefix=0u; s_k=500; }
  __syncthreads();

  for (int pass=0; pass<4; pass++){
    int shift = 24 - 8*pass;
    unsigned hi_mask = (pass==0) ? 0u : (0xFFFFFFFFu << (shift+8));
    if (tid < 256) hist[tid]=0u;
    __syncthreads();
    unsigned pfx = s_prefix;
    int kk = s_k;
    for (int i=tid;i<4096;i+=1024){
      unsigned bits = __float_as_uint(fv[i]);
      unsigned u = (bits & 0x80000000u) ? ~bits : (bits | 0x80000000u);
      if ((u & hi_mask) == pfx) atomicAdd(&hist[(u>>shift)&255u], 1u);
    }
    __syncthreads();
    if (tid<32){
      int base=tid*8;
      unsigned c[8];
      #pragma unroll
      for (int j=0;j<8;j++) c[j]=hist[base+j];
      unsigned tot=0;
      #pragma unroll
      for (int j=0;j<8;j++) tot+=c[j];
      unsigned suf=tot;
      #pragma unroll
      for (int off=1;off<32;off<<=1){
        unsigned n=__shfl_down_sync(0xffffffffu, suf, off);
        if (lane+off<32) suf+=n;
      }
      unsigned run = suf - tot;
      #pragma unroll
      for (int j=7;j>=0;j--){ run += c[j]; hist[base+j]=run; }
    }
    __syncthreads();
    if (tid<256){
      unsigned ge = hist[tid];
      unsigned gt = (tid<255) ? hist[tid+1] : 0u;
      if (ge >= (unsigned)kk && gt < (unsigned)kk){
        s_prefix = pfx | ((unsigned)tid << shift);
        s_k = kk - (int)gt;
      }
    }
    __syncthreads();
  }
  unsigned u = s_prefix;
  unsigned tbits = (u & 0x80000000u) ? (u ^ 0x80000000u) : ~u;
  float thr = __uint_as_float(tbits);

  int srv[4];
  int mycnt = 0;
  #pragma unroll
  for (int j=0;j<4;j++){
    int i = tid*4 + j;
    float v = fv[i];
    int s = -1;
    if (v>0.0f && v>=thr){
      int by=i>>6, bx=i&63;
      int p = pos[i];
      int y=p>>9, x=p&511;
      bool ok = true;
      #pragma unroll
      for (int dby=-1;dby<=1;dby++)
        #pragma unroll
        for (int dbx=-1;dbx<=1;dbx++){
          if (dby==0 && dbx==0) continue;
          int nby=by+dby, nbx=bx+dbx;
          if (nby<0||nby>63||nbx<0||nbx>63) continue;
          int n = nby*64+nbx;
          float nv = fv[n];
          if (nv>v && nv>=thr){
            int np = pos[n];
            int ny=np>>9, nx=np&511;
            if (abs(ny-y)<=2 && abs(nx-x)<=2) ok=false;
          }
        }
      s = ok ? p : -1;
    }
    srv[j]=s;
    mycnt += (s>=0);
  }
  int v = mycnt;
  #pragma unroll
  for (int off=1;off<32;off<<=1){
    int n=__shfl_up_sync(0xffffffffu, v, off);
    if (lane>=off) v+=n;
  }
  if (lane==31) wsum[wid]=v;
  __syncthreads();
  if (wid==0){
    int s=wsum[lane];
    #pragma unroll
    for (int off=1;off<32;off<<=1){
      int n=__shfl_up_sync(0xffffffffu, s, off);
      if (lane>=off) s+=n;
    }
    wsum[lane]=s;
  }
  __syncthreads();
  int offs = (wid ? wsum[wid-1] : 0) + v - mycnt;
  #pragma unroll
  for (int j=0;j<4;j++){
    if (srv[j]>=0){
      if (offs < LCAP) g_list[img*LCAP + offs] = srv[j];
      offs++;
    }
  }
  if (tid==1023){
    int tot = wsum[31];
    g_cnt[img] = tot > LCAP ? LCAP : tot;
  }
}

// ============ K4: warp-per-survivor correction + fused final reduction ============
__global__ __launch_bounds__(1024) void k4(const float* __restrict__ scores,
                                           float* __restrict__ out){
  const int tid = threadIdx.x;
  const int wid = tid>>5, lane = tid&31;
  const int w32 = blockIdx.x*32 + wid;
  const int img = w32 / LCAP;
  const int idx = w32 - img*LCAP;
  __shared__ float wsumf[32];
  __shared__ bool isLast;
  float acc = 0.0f;
  if (idx < g_cnt[img]){
    const int s = g_list[w32];
    const float* sp = scores + (size_t)img*HW*HW;
    float wk[7]; gw7(wk);
    const int y = s>>9, x = s&511;
    #pragma unroll
    for (int t=lane; t<49; t+=32){
      int ky=t/7, kx=t-ky*7;
      int yy = refl512(y+ky-3);
      int xx = refl512(x+kx-3);
      float p = sp[yy*HW+xx];
      float lp = fmaxf(logf(p), -100.0f);
      float l1 = fmaxf(log1pf(-p), -100.0f);
      acc += wk[ky]*wk[kx]*(lp - l1);
    }
  }
  #pragma unroll
  for (int off=16;off;off>>=1) acc += __shfl_down_sync(0xffffffffu, acc, off);
  if (lane==0) wsumf[wid]=acc;
  __syncthreads();
  if (tid==0){
    double s=0.0;
    for (int i=0;i<32;i++) s += (double)wsumf[i];
    g_pc[blockIdx.x]=s;
    __threadfence();
    unsigned t = atomicAdd(&g_arrive, 1u);
    isLast = (t == (unsigned)(gridDim.x-1));
  }
  __syncthreads();
  if (!isLast) return;

  __shared__ double sb[1024], sr[1024], sx[1024];
  double bsum=0.0, rsum=0.0;
  for (int i=tid;i<4096;i+=1024){ bsum += g_pb[i]; rsum += g_pr[i]; }
  double csum = (tid<K4CTAS) ? g_pc[tid] : 0.0;
  sb[tid]=bsum; sr[tid]=rsum; sx[tid]=csum;
  __syncthreads();
  for (int s=512;s;s>>=1){
    if (tid<s){ sb[tid]+=sb[tid+s]; sr[tid]+=sr[tid+s]; sx[tid]+=sx[tid+s]; }
    __syncthreads();
  }
  if (tid==0){
    double n = (double)NPIX;
    out[0] = (float)((sb[0]-sx[0])/n + (sr[0]/n)*10.0);
    g_arrive = 0u;
  }
}

// ---------------- launch ----------------
extern "C" void kernel_launch(void* const* d_in, const int* in_sizes, int n_in,
                              void* d_out, int out_size){
  const float* scores = (const float*)d_in[0];
  const float* imgs   = (const float*)d_in[1];
  if (in_sizes[0] != NB*1*HW*HW){
    const float* tmp = scores; scores = imgs; imgs = tmp;
  }
  dim3 blk(32,32), grd(16,16,NB);
  kmain<<<grd, blk>>>(imgs, scores);
  k2<<<NB, 1024>>>();
  k4<<<K4CTAS, 1024>>>(scores, (float*)d_out);
}

// round 8
// speedup vs baseline: 1.3041x; 1.3041x over previous
#include <cuda_runtime.h>
#include <math.h>

#define NB 16
#define HW 512
#define NPIX (NB*HW*HW)
#define LCAP 768
#define K4CTAS (NB*LCAP/32)   // 384

// ---------------- device scratch ----------------
__device__ float    g_bval[NB*4096];
__device__ int      g_bpos[NB*4096];
__device__ int      g_list[NB*LCAP];
__device__ int      g_cnt[NB];
__device__ double   g_pb[4096];
__device__ double   g_pr[4096];
__device__ double   g_pc[K4CTAS];
__device__ unsigned g_arrive;

__device__ __forceinline__ int refl512(int i){ return i<0 ? -i : (i>511 ? 1022-i : i); }
__device__ __forceinline__ int clamp512(int i){ return i<0?0:(i>511?511:i); }

__device__ __forceinline__ void gw7(float* w){
  float e0=expf(-4.5f), e1=expf(-2.0f), e2=expf(-0.5f);
  float s=1.0f+2.0f*(e0+e1+e2);
  w[0]=e0/s; w[1]=e1/s; w[2]=e2/s; w[3]=1.0f/s; w[4]=w[2]; w[5]=w[1]; w[6]=w[0];
}

// dynamic smem layout (floats)
#define OFF_P   0        // 42x44 float4 = 7392 floats
#define OFF_T   7392     // 42x36 float4 = 6048 floats
#define OFF_SG  13440    // 44x48 = 2112
#define OFF_RB  15552    // 32
#define OFF_RR  15584    // 32
#define BUFSZ   15616    // 62464 bytes

// ============ KMAIN: [scores lap/bce/reg] + [gray->sobel->ST->gauss7->mineig->NMS->blockmax] ============
__global__ __launch_bounds__(1024) void kmain(const float* __restrict__ imgs,
                                              const float* __restrict__ scores){
  const int b = blockIdx.z;
  const int ty0 = blockIdx.y*32, tx0 = blockIdx.x*32;
  extern __shared__ __align__(16) float buf[];
  float* p4  = buf + OFF_P;    // (dx2, dy2, dxy, -) per pixel
  float* t4  = buf + OFF_T;    // row-blurred trio per pixel
  float* sg  = buf + OFF_SG;   // gray 44 x 48 (cols 0..45 valid)
  float* resp= buf + OFF_SG;   // 36x36, aliases sg (dead after B)
  float* rm  = buf;            // 36x32, aliases p4 (dead after C)
  float* sv  = buf + 1152;     // 32x32
  float* sc  = buf;            // phase0: 36x36
  float* rs  = buf + 1296;     // phase0: 36x32
  float* rb  = buf + OFF_RB;
  float* rr2 = buf + OFF_RR;

  const int ty = threadIdx.y, tx = threadIdx.x;
  const int tid = ty*32 + tx;
  const float NEG = __int_as_float(0xff800000u);

  const float* rrp = imgs + (size_t)b*3*HW*HW;
  const float* ggp = rrp + HW*HW;
  const float* bbp = ggp + HW*HW;
  const float* sp  = scores + (size_t)b*HW*HW;

  // ---- load scores tile (36x36) and gray tile (44x46), one barrier ----
  for (int i=tid;i<1296;i+=1024){
    int iy=i/36, ix=i%36;
    sc[i] = sp[refl512(ty0-2+iy)*HW + refl512(tx0-2+ix)];
  }
  for (int i=tid;i<2024;i+=1024){      // 44*46
    int iy=i/46, ix=i%46;
    int gy=clamp512(ty0-6+iy), gx=clamp512(tx0-6+ix);
    int o=gy*HW+gx;
    sg[iy*48+ix] = 0.299f*rrp[o] + 0.587f*ggp[o] + 0.114f*bbp[o];
  }
  __syncthreads();

  // ---- phase0a: row sums of 5 ----
  for (int i=tid;i<1152;i+=1024){
    int iy=i/32, x=i%32;
    int base=iy*36+x;
    rs[i] = sc[base]+sc[base+1]+sc[base+2]+sc[base+3]+sc[base+4];
  }
  __syncthreads();
  // ---- phase0b: laplacian + reg + base bce ----
  {
    const int oy=ty, ox=tx;
    float S = rs[oy*32+ox]+rs[(oy+1)*32+ox]+rs[(oy+2)*32+ox]+rs[(oy+3)*32+ox]+rs[(oy+4)*32+ox];
    float p = sc[(oy+2)*36 + ox+2];
    float lap = (S - 25.0f*p) * (1.0f/48.0f);
    float v2 = p * expf(-lap);
    float v1 = -fmaxf(log1pf(-p), -100.0f);
    #pragma unroll
    for (int off=16;off;off>>=1){
      v1 += __shfl_down_sync(0xffffffffu, v1, off);
      v2 += __shfl_down_sync(0xffffffffu, v2, off);
    }
    if ((tid&31)==0){ rb[tid>>5]=v1; rr2[tid>>5]=v2; }
  }
  __syncthreads();
  if (tid<32){
    float a1=rb[tid], a2=rr2[tid];
    #pragma unroll
    for (int off=16;off;off>>=1){
      a1 += __shfl_down_sync(0xffffffffu, a1, off);
      a2 += __shfl_down_sync(0xffffffffu, a2, off);
    }
    if (tid==0){
      int bid = (blockIdx.z*16 + blockIdx.y)*16 + blockIdx.x;
      g_pb[bid]=(double)a1; g_pr[bid]=(double)a2;
    }
  }
  __syncthreads();   // sc/rs dead; B may overwrite

  // ---- B: gradient products at reflected coords, 42x42, one STS.128 each ----
  for (int i=tid; i<1764; i+=1024){
    int iy=i/42, ix=i-iy*42;
    int qy=refl512(ty0-5+iy), qx=refl512(tx0-5+ix);
    int ly=qy-ty0+6, lx=qx-tx0+6;
    const float* c0=&sg[(ly-1)*48+lx];
    const float* c1=&sg[ ly   *48+lx];
    const float* c2=&sg[(ly+1)*48+lx];
    float a=c0[-1], b_=c0[0], c=c0[1];
    float d=c1[-1],            e=c1[1];
    float f=c2[-1], h=c2[0],  k=c2[1];
    float dx=(c-a+2.0f*(e-d)+k-f)*0.125f;
    float dy=(f-a+2.0f*(h-b_)+k-c)*0.125f;
    *(float4*)&p4[4*(iy*44+ix)] = make_float4(dx*dx, dy*dy, dx*dy, 0.0f);
  }
  __syncthreads();

  float w[7]; gw7(w);

  // ---- C: row blur, 42 rows x 18 x-pairs (756 units); 8 LDS.128 -> 2 STS.128 ----
  for (int i=tid; i<756; i+=1024){
    int iy=i/18, j=i-iy*18;
    int x0=2*j;
    int base=4*(iy*44+x0);
    float a0=0.f,a1=0.f,a2=0.f, b0=0.f,b1=0.f,b2=0.f;
    #pragma unroll
    for (int k=0;k<8;k++){
      float4 q = *(const float4*)&p4[base+4*k];
      if (k<7){ a0+=w[k]*q.x;   a1+=w[k]*q.y;   a2+=w[k]*q.z; }
      if (k>0){ b0+=w[k-1]*q.x; b1+=w[k-1]*q.y; b2+=w[k-1]*q.z; }
    }
    int o = 4*(iy*36+x0);
    *(float4*)&t4[o]   = make_float4(a0,a1,a2,0.0f);
    *(float4*)&t4[o+4] = make_float4(b0,b1,b2,0.0f);
  }
  __syncthreads();

  // ---- D: col blur + min eigenvalue, 18 y-pairs x 36 cols (648 units); 8 LDS.128 ----
  for (int i=tid; i<648; i+=1024){
    int row=i/36, x=i-row*36;
    int iy=2*row;
    float a0=0.f,a1=0.f,a2=0.f, b0=0.f,b1=0.f,b2=0.f;
    #pragma unroll
    for (int k=0;k<8;k++){
      float4 q = *(const float4*)&t4[4*((iy+k)*36+x)];
      if (k<7){ a0+=w[k]*q.x;   a1+=w[k]*q.y;   a2+=w[k]*q.z; }
      if (k>0){ b0+=w[k-1]*q.x; b1+=w[k-1]*q.y; b2+=w[k-1]*q.z; }
    }
    {
      float det=a0*a1-a2*a2, tr=a0+a1;
      float r0=0.5f*(tr - sqrtf(fabsf(tr*tr - 4.0f*det)));
      int ry=ty0-2+iy, rx=tx0-2+x;
      resp[iy*36+x] = (ry>=0 && ry<HW && rx>=0 && rx<HW) ? r0 : NEG;
    }
    {
      float det=b0*b1-b2*b2, tr=b0+b1;
      float r1=0.5f*(tr - sqrtf(fabsf(tr*tr - 4.0f*det)));
      int ry=ty0-1+iy, rx=tx0-2+x;
      resp[(iy+1)*36+x] = (ry>=0 && ry<HW && rx>=0 && rx<HW) ? r1 : NEG;
    }
  }
  __syncthreads();

  // ---- E0: row max of 5, 36x32 ----
  for (int i=tid;i<1152;i+=1024){
    int iy=i/32, x=i-iy*32;
    int base=iy*36+x;
    float m = fmaxf(fmaxf(fmaxf(resp[base],resp[base+1]),fmaxf(resp[base+2],resp[base+3])),resp[base+4]);
    rm[i]=m;
  }
  __syncthreads();
  // ---- E1: col max -> NMS ----
  {
    const int oy=ty, ox=tx;
    float v = resp[(oy+2)*36 + ox+2];
    float m = fmaxf(fmaxf(fmaxf(rm[oy*32+ox],rm[(oy+1)*32+ox]),
                          fmaxf(rm[(oy+2)*32+ox],rm[(oy+3)*32+ox])),rm[(oy+4)*32+ox]);
    sv[oy*32+ox] = (v==m) ? v : 0.0f;
  }
  __syncthreads();
  // ---- E2: per-8x8-block max ----
  if ((ty&7)==0 && (tx&7)==0){
    float bv = sv[ty*32+tx];
    int   bp = (ty0+ty)*HW + (tx0+tx);
    for (int i=0;i<8;i++)
      for (int j=0;j<8;j++){
        float q = sv[(ty+i)*32 + tx+j];
        if (q > bv){ bv=q; bp=(ty0+ty+i)*HW + (tx0+tx+j); }
      }
    int bidx = b*4096 + ((ty0+ty)>>3)*64 + ((tx0+tx)>>3);
    g_bval[bidx]=bv; g_bpos[bidx]=bp;
  }
}

// ============ K2: radix-select + select + second NMS + deterministic compaction ============
__global__ __launch_bounds__(1024) void k2(){
  const int img = blockIdx.x, tid = threadIdx.x;
  const int lane = tid&31, wid = tid>>5;
  __shared__ float fv[4096];
  __shared__ int   pos[4096];
  __shared__ unsigned hist[256];
  __shared__ int wsum[32];
  __shared__ unsigned s_prefix;
  __shared__ int s_k;
  for (int i=tid;i<4096;i+=1024){
    fv[i]=g_bval[img*4096+i];
    pos[i]=g_bpos[img*4096+i];
  }
  if (tid==0){ s_prefix=0u; s_k=500; }
  __syncthreads();

  for (int pass=0; pass<4; pass++){
    int shift = 24 - 8*pass;
    unsigned hi_mask = (pass==0) ? 0u : (0xFFFFFFFFu << (shift+8));
    if (tid < 256) hist[tid]=0u;
    __syncthreads();
    unsigned pfx = s_prefix;
    int kk = s_k;
    for (int i=tid;i<4096;i+=1024){
      unsigned bits = __float_as_uint(fv[i]);
      unsigned u = (bits & 0x80000000u) ? ~bits : (bits | 0x80000000u);
      if ((u & hi_mask) == pfx) atomicAdd(&hist[(u>>shift)&255u], 1u);
    }
    __syncthreads();
    if (tid<32){
      int base=tid*8;
      unsigned c[8];
      #pragma unroll
      for (int j=0;j<8;j++) c[j]=hist[base+j];
      unsigned tot=0;
      #pragma unroll
      for (int j=0;j<8;j++) tot+=c[j];
      unsigned suf=tot;
      #pragma unroll
      for (int off=1;off<32;off<<=1){
        unsigned n=__shfl_down_sync(0xffffffffu, suf, off);
        if (lane+off<32) suf+=n;
      }
      unsigned run = suf - tot;
      #pragma unroll
      for (int j=7;j>=0;j--){ run += c[j]; hist[base+j]=run; }
    }
    __syncthreads();
    if (tid<256){
      unsigned ge = hist[tid];
      unsigned gt = (tid<255) ? hist[tid+1] : 0u;
      if (ge >= (unsigned)kk && gt < (unsigned)kk){
        s_prefix = pfx | ((unsigned)tid << shift);
        s_k = kk - (int)gt;
      }
    }
    __syncthreads();
  }
  unsigned u = s_prefix;
  unsigned tbits = (u & 0x80000000u) ? (u ^ 0x80000000u) : ~u;
  float thr = __uint_as_float(tbits);

  int srv[4];
  int mycnt = 0;
  #pragma unroll
  for (int j=0;j<4;j++){
    int i = tid*4 + j;
    float v = fv[i];
    int s = -1;
    if (v>0.0f && v>=thr){
      int by=i>>6, bx=i&63;
      int p = pos[i];
      int y=p>>9, x=p&511;
      bool ok = true;
      #pragma unroll
      for (int dby=-1;dby<=1;dby++)
        #pragma unroll
        for (int dbx=-1;dbx<=1;dbx++){
          if (dby==0 && dbx==0) continue;
          int nby=by+dby, nbx=bx+dbx;
          if (nby<0||nby>63||nbx<0||nbx>63) continue;
          int n = nby*64+nbx;
          float nv = fv[n];
          if (nv>v && nv>=thr){
            int np = pos[n];
            int ny=np>>9, nx=np&511;
            if (abs(ny-y)<=2 && abs(nx-x)<=2) ok=false;
          }
        }
      s = ok ? p : -1;
    }
    srv[j]=s;
    mycnt += (s>=0);
  }
  int v = mycnt;
  #pragma unroll
  for (int off=1;off<32;off<<=1){
    int n=__shfl_up_sync(0xffffffffu, v, off);
    if (lane>=off) v+=n;
  }
  if (lane==31) wsum[wid]=v;
  __syncthreads();
  if (wid==0){
    int s=wsum[lane];
    #pragma unroll
    for (int off=1;off<32;off<<=1){
      int n=__shfl_up_sync(0xffffffffu, s, off);
      if (lane>=off) s+=n;
    }
    wsum[lane]=s;
  }
  __syncthreads();
  int offs = (wid ? wsum[wid-1] : 0) + v - mycnt;
  #pragma unroll
  for (int j=0;j<4;j++){
    if (srv[j]>=0){
      if (offs < LCAP) g_list[img*LCAP + offs] = srv[j];
      offs++;
    }
  }
  if (tid==1023){
    int tot = wsum[31];
    g_cnt[img] = tot > LCAP ? LCAP : tot;
  }
}

// ============ K4: warp-per-survivor correction + fused final reduction ============
__global__ __launch_bounds__(1024) void k4(const float* __restrict__ scores,
                                           float* __restrict__ out){
  const int tid = threadIdx.x;
  const int wid = tid>>5, lane = tid&31;
  const int w32 = blockIdx.x*32 + wid;
  const int img = w32 / LCAP;
  const int idx = w32 - img*LCAP;
  __shared__ float wsumf[32];
  __shared__ bool isLast;
  float acc = 0.0f;
  if (idx < g_cnt[img]){
    const int s = g_list[w32];
    const float* sp = scores + (size_t)img*HW*HW;
    float wk[7]; gw7(wk);
    const int y = s>>9, x = s&511;
    #pragma unroll
    for (int t=lane; t<49; t+=32){
      int ky=t/7, kx=t-ky*7;
      int yy = refl512(y+ky-3);
      int xx = refl512(x+kx-3);
      float p = sp[yy*HW+xx];
      float lp = fmaxf(logf(p), -100.0f);
      float l1 = fmaxf(log1pf(-p), -100.0f);
      acc += wk[ky]*wk[kx]*(lp - l1);
    }
  }
  #pragma unroll
  for (int off=16;off;off>>=1) acc += __shfl_down_sync(0xffffffffu, acc, off);
  if (lane==0) wsumf[wid]=acc;
  __syncthreads();
  if (tid==0){
    double s=0.0;
    for (int i=0;i<32;i++) s += (double)wsumf[i];
    g_pc[blockIdx.x]=s;
    __threadfence();
    unsigned t = atomicAdd(&g_arrive, 1u);
    isLast = (t == (unsigned)(gridDim.x-1));
  }
  __syncthreads();
  if (!isLast) return;

  __shared__ double sb[1024], sr[1024], sx[1024];
  double bsum=0.0, rsum=0.0;
  for (int i=tid;i<4096;i+=1024){ bsum += g_pb[i]; rsum += g_pr[i]; }
  double csum = (tid<K4CTAS) ? g_pc[tid] : 0.0;
  sb[tid]=bsum; sr[tid]=rsum; sx[tid]=csum;
  __syncthreads();
  for (int s=512;s;s>>=1){
    if (tid<s){ sb[tid]+=sb[tid+s]; sr[tid]+=sr[tid+s]; sx[tid]+=sx[tid+s]; }
    __syncthreads();
  }
  if (tid==0){
    double n = (double)NPIX;
    out[0] = (float)((sb[0]-sx[0])/n + (sr[0]/n)*10.0);
    g_arrive = 0u;
  }
}

// ---------------- launch ----------------
extern "C" void kernel_launch(void* const* d_in, const int* in_sizes, int n_in,
                              void* d_out, int out_size){
  const float* scores = (const float*)d_in[0];
  const float* imgs   = (const float*)d_in[1];
  if (in_sizes[0] != NB*1*HW*HW){
    const float* tmp = scores; scores = imgs; imgs = tmp;
  }
  const int smem_bytes = BUFSZ*4;  // 62464
  static int configured = 0;
  if (!configured){
    cudaFuncSetAttribute(kmain, cudaFuncAttributeMaxDynamicSharedMemorySize, smem_bytes);
    configured = 1;
  }
  dim3 blk(32,32), grd(16,16,NB);
  kmain<<<grd, blk, smem_bytes>>>(imgs, scores);
  k2<<<NB, 1024>>>();
  k4<<<K4CTAS, 1024>>>(scores, (float*)d_out);
}

// round 9
// speedup vs baseline: 1.8557x; 1.4230x over previous
#include <cuda_runtime.h>
#include <math.h>

#define NB 16
#define HW 512
#define NPIX (NB*HW*HW)
#define LCAP 768
#define K4CTAS (NB*LCAP/32)   // 384
#define NPART 2048            // kmain CTAs

// ---------------- device scratch ----------------
__device__ float    g_bval[NB*4096];
__device__ int      g_bpos[NB*4096];
__device__ int      g_list[NB*LCAP];
__device__ int      g_cnt[NB];
__device__ double   g_pb[NPART];
__device__ double   g_pr[NPART];
__device__ double   g_pc[K4CTAS];
__device__ unsigned g_arrive;

__device__ __forceinline__ int refl512(int i){ return i<0 ? -i : (i>511 ? 1022-i : i); }
__device__ __forceinline__ int clamp512(int i){ return i<0?0:(i>511?511:i); }

__device__ __forceinline__ void gw7(float* w){
  float e0=__expf(-4.5f), e1=__expf(-2.0f), e2=__expf(-0.5f);
  float s=1.0f+2.0f*(e0+e1+e2);
  w[0]=e0/s; w[1]=e1/s; w[2]=e2/s; w[3]=1.0f/s; w[4]=w[2]; w[5]=w[1]; w[6]=w[0];
}

__device__ __forceinline__ float fsqrt_pos(float z){
  // z >= 0; fast sqrt robust at z==0
  return (z > 1e-37f) ? z*__frsqrt_rn(z) : 0.0f;
}

// smem layout (floats). Tile: 64 wide x 32 tall output.
#define OFF_SG  0       // gray: 44 rows x 76
#define OFF_SC  3344    // scores: 36 x 68
#define OFF_RS  5792    // row box sums: 36 x 64
#define OFF_P0  8096    // 42 x 76
#define OFF_P1  11288
#define OFF_P2  14480
#define OFF_T0  17672   // 42 x 68
#define OFF_T1  20528
#define OFF_T2  23384
#define OFF_RB  26240   // 32
#define OFF_RR  26272   // 32
#define BUFSZ   26304   // 105216 bytes

// ============ KMAIN: [scores lap/bce/reg] + [gray->sobel->ST->gauss7->mineig->NMS->blockmax] ============
__global__ __launch_bounds__(1024,2) void kmain(const float* __restrict__ imgs,
                                                const float* __restrict__ scores){
  const int b = blockIdx.z;
  const int ty0 = blockIdx.y*32, tx0 = blockIdx.x*64;
  extern __shared__ __align__(16) float buf[];
  float* sg = buf + OFF_SG;
  float* sc = buf + OFF_SC;
  float* rs = buf + OFF_RS;
  float* p0 = buf + OFF_P0;
  float* p1 = buf + OFF_P1;
  float* p2 = buf + OFF_P2;
  float* t0 = buf + OFF_T0;
  float* t1 = buf + OFF_T1;
  float* t2 = buf + OFF_T2;
  float* rb = buf + OFF_RB;
  float* rr2= buf + OFF_RR;
  float* resp = buf + OFF_SG;   // 36x68, aliases sg (dead after B)
  float* rm   = buf + OFF_SC;   // 36x64, aliases sc (dead after phase0b)
  float* sv   = buf + OFF_RS;   // 32x64, aliases rs (dead after phase0b)

  const int ty = threadIdx.y, tx = threadIdx.x;
  const int tid = ty*32 + tx;
  const float NEG = __int_as_float(0xff800000u);
  const bool interior = (blockIdx.x-1u < 6u) && (blockIdx.y-1u < 14u);

  const float* rrp = imgs + (size_t)b*3*HW*HW;
  const float* ggp = rrp + HW*HW;
  const float* bbp = ggp + HW*HW;
  const float* sp  = scores + (size_t)b*HW*HW;

  // ---- loads: scores 36x68 and gray 44x76, register-indexed 2D loops ----
  if (interior){
    for (int iy=ty; iy<36; iy+=32){
      const float* r = sp + (ty0-2+iy)*HW + tx0-2;
      for (int ix=tx; ix<68; ix+=32) sc[iy*68+ix] = r[ix];
    }
    for (int iy=ty; iy<44; iy+=32){
      int o0 = (ty0-6+iy)*HW + tx0-6;
      for (int ix=tx; ix<76; ix+=32){
        int o=o0+ix;
        sg[iy*76+ix] = 0.299f*rrp[o] + 0.587f*ggp[o] + 0.114f*bbp[o];
      }
    }
  } else {
    for (int iy=ty; iy<36; iy+=32){
      int gy = refl512(ty0-2+iy);
      for (int ix=tx; ix<68; ix+=32) sc[iy*68+ix] = sp[gy*HW + refl512(tx0-2+ix)];
    }
    for (int iy=ty; iy<44; iy+=32){
      int gy = clamp512(ty0-6+iy);
      for (int ix=tx; ix<76; ix+=32){
        int o = gy*HW + clamp512(tx0-6+ix);
        sg[iy*76+ix] = 0.299f*rrp[o] + 0.587f*ggp[o] + 0.114f*bbp[o];
      }
    }
  }
  __syncthreads();

  // ---- phase0a: row sums of 5 (36 x 64) ----
  for (int iy=ty; iy<36; iy+=32){
    for (int ix=tx; ix<64; ix+=32){
      int base=iy*68+ix;
      rs[iy*64+ix] = sc[base]+sc[base+1]+sc[base+2]+sc[base+3]+sc[base+4];
    }
  }
  __syncthreads();

  // ---- phase0b: laplacian + reg + base bce (32 x 64, 2 outputs/thread) ----
  {
    float v1=0.f, v2=0.f;
    const int oy=ty;
    #pragma unroll
    for (int t=0;t<2;t++){
      int ox = tx + 32*t;
      float S = rs[oy*64+ox]+rs[(oy+1)*64+ox]+rs[(oy+2)*64+ox]+rs[(oy+3)*64+ox]+rs[(oy+4)*64+ox];
      float p = sc[(oy+2)*68 + ox+2];
      float lap = (S - 25.0f*p) * (1.0f/48.0f);
      v2 += p * __expf(-lap);
      v1 += -fmaxf(__logf(1.0f-p), -100.0f);
    }
    #pragma unroll
    for (int off=16;off;off>>=1){
      v1 += __shfl_down_sync(0xffffffffu, v1, off);
      v2 += __shfl_down_sync(0xffffffffu, v2, off);
    }
    if ((tid&31)==0){ rb[tid>>5]=v1; rr2[tid>>5]=v2; }
  }
  __syncthreads();   // sc/rs reads done; rb ready; B may start
  if (tid<32){
    float a1=rb[tid], a2=rr2[tid];
    #pragma unroll
    for (int off=16;off;off>>=1){
      a1 += __shfl_down_sync(0xffffffffu, a1, off);
      a2 += __shfl_down_sync(0xffffffffu, a2, off);
    }
    if (tid==0){
      int bid = (b*16 + blockIdx.y)*8 + blockIdx.x;
      g_pb[bid]=(double)a1; g_pr[bid]=(double)a2;
    }
  }

  // ---- B: gradient products at reflected coords, 42 x 74 ----
  for (int iy=ty; iy<42; iy+=32){
    int qy = refl512(ty0-5+iy);
    int ly = qy - ty0 + 6;
    const float* c0 = &sg[(ly-1)*76];
    const float* c1 = &sg[ ly   *76];
    const float* c2 = &sg[(ly+1)*76];
    for (int ix=tx; ix<74; ix+=32){
      int qx = refl512(tx0-5+ix);
      int lx = qx - tx0 + 6;
      float a=c0[lx-1], b_=c0[lx], c=c0[lx+1];
      float d=c1[lx-1],            e=c1[lx+1];
      float f=c2[lx-1], h=c2[lx],  k=c2[lx+1];
      float dx=(c-a+2.0f*(e-d)+k-f)*0.125f;
      float dy=(f-a+2.0f*(h-b_)+k-c)*0.125f;
      int o = iy*76+ix;
      p0[o]=dx*dx; p1[o]=dy*dy; p2[o]=dx*dy;
    }
  }
  __syncthreads();

  float w[7]; gw7(w);

  // ---- C: row blur, 42 rows x 34 x-pairs ----
  for (int iy=ty; iy<42; iy+=32){
    for (int xp=tx; xp<34; xp+=32){
      int x0=2*xp;
      int base=iy*76+x0;
      float a0=0.f,a1=0.f,a2=0.f, b0=0.f,b1=0.f,b2=0.f;
      #pragma unroll
      for (int k=0;k<8;k++){
        float q0=p0[base+k], q1=p1[base+k], q2=p2[base+k];
        if (k<7){ a0+=w[k]*q0;   a1+=w[k]*q1;   a2+=w[k]*q2; }
        if (k>0){ b0+=w[k-1]*q0; b1+=w[k-1]*q1; b2+=w[k-1]*q2; }
      }
      int o = iy*68+x0;
      t0[o]=a0; t1[o]=a1; t2[o]=a2;
      t0[o+1]=b0; t1[o+1]=b1; t2[o+1]=b2;
    }
  }
  __syncthreads();

  // ---- D: col blur + min eigenvalue, 18 y-pairs x 68 cols (1224 units) ----
  for (int i=tid; i<1224; i+=1024){
    int row=i/68, x=i-row*68;
    int iy=2*row;
    float a0=0.f,a1=0.f,a2=0.f, b0=0.f,b1=0.f,b2=0.f;
    #pragma unroll
    for (int k=0;k<8;k++){
      int o=(iy+k)*68+x;
      float q0=t0[o], q1=t1[o], q2=t2[o];
      if (k<7){ a0+=w[k]*q0;   a1+=w[k]*q1;   a2+=w[k]*q2; }
      if (k>0){ b0+=w[k-1]*q0; b1+=w[k-1]*q1; b2+=w[k-1]*q2; }
    }
    {
      float det=a0*a1-a2*a2, tr=a0+a1;
      float r0=0.5f*(tr - fsqrt_pos(fabsf(tr*tr - 4.0f*det)));
      int ry=ty0-2+iy, rx=tx0-2+x;
      resp[iy*68+x] = (ry>=0 && ry<HW && rx>=0 && rx<HW) ? r0 : NEG;
    }
    {
      float det=b0*b1-b2*b2, tr=b0+b1;
      float r1=0.5f*(tr - fsqrt_pos(fabsf(tr*tr - 4.0f*det)));
      int ry=ty0-1+iy, rx=tx0-2+x;
      resp[(iy+1)*68+x] = (ry>=0 && ry<HW && rx>=0 && rx<HW) ? r1 : NEG;
    }
  }
  __syncthreads();

  // ---- E0: row max of 5, 36 x 64 ----
  for (int iy=ty; iy<36; iy+=32){
    for (int ix=tx; ix<64; ix+=32){
      int base=iy*68+ix;
      rm[iy*64+ix] = fmaxf(fmaxf(fmaxf(resp[base],resp[base+1]),
                                 fmaxf(resp[base+2],resp[base+3])),resp[base+4]);
    }
  }
  __syncthreads();

  // ---- E1: col max of 5 -> NMS, 32 x 64 ----
  {
    const int oy=ty;
    #pragma unroll
    for (int t=0;t<2;t++){
      int ox = tx + 32*t;
      float v = resp[(oy+2)*68 + ox+2];
      float m = fmaxf(fmaxf(fmaxf(rm[oy*64+ox],rm[(oy+1)*64+ox]),
                            fmaxf(rm[(oy+2)*64+ox],rm[(oy+3)*64+ox])),rm[(oy+4)*64+ox]);
      sv[oy*64+ox] = (v==m) ? v : 0.0f;
    }
  }
  __syncthreads();

  // ---- E2: per-8x8-block max, 4x8 = 32 blocks, one thread each ----
  if (tid < 32){
    int by = tid>>3, bx = tid&7;
    int y0 = by*8, x0 = bx*8;
    float bv = sv[y0*64+x0];
    int   bp = (ty0+y0)*HW + (tx0+x0);
    for (int r=0;r<8;r++)
      for (int j=0;j<8;j++){
        float q = sv[(y0+r)*64 + x0+j];
        if (q > bv){ bv=q; bp=(ty0+y0+r)*HW + (tx0+x0+j); }
      }
    int bidx = b*4096 + ((ty0>>3)+by)*64 + (tx0>>3)+bx;
    g_bval[bidx]=bv; g_bpos[bidx]=bp;
  }
}

// ============ K2: radix-select + select + second NMS + deterministic compaction ============
__global__ __launch_bounds__(1024) void k2(){
  const int img = blockIdx.x, tid = threadIdx.x;
  const int lane = tid&31, wid = tid>>5;
  __shared__ float fv[4096];
  __shared__ int   pos[4096];
  __shared__ unsigned hist[256];
  __shared__ int wsum[32];
  __shared__ unsigned s_prefix;
  __shared__ int s_k;
  for (int i=tid;i<4096;i+=1024){
    fv[i]=g_bval[img*4096+i];
    pos[i]=g_bpos[img*4096+i];
  }
  if (tid==0){ s_prefix=0u; s_k=500; }
  __syncthreads();

  for (int pass=0; pass<4; pass++){
    int shift = 24 - 8*pass;
    unsigned hi_mask = (pass==0) ? 0u : (0xFFFFFFFFu << (shift+8));
    if (tid < 256) hist[tid]=0u;
    __syncthreads();
    unsigned pfx = s_prefix;
    int kk = s_k;
    for (int i=tid;i<4096;i+=1024){
      unsigned bits = __float_as_uint(fv[i]);
      unsigned u = (bits & 0x80000000u) ? ~bits : (bits | 0x80000000u);
      if ((u & hi_mask) == pfx) atomicAdd(&hist[(u>>shift)&255u], 1u);
    }
    __syncthreads();
    if (tid<32){
      int base=tid*8;
      unsigned c[8];
      #pragma unroll
      for (int j=0;j<8;j++) c[j]=hist[base+j];
      unsigned tot=0;
      #pragma unroll
      for (int j=0;j<8;j++) tot+=c[j];
      unsigned suf=tot;
      #pragma unroll
      for (int off=1;off<32;off<<=1){
        unsigned n=__shfl_down_sync(0xffffffffu, suf, off);
        if (lane+off<32) suf+=n;
      }
      unsigned run = suf - tot;
      #pragma unroll
      for (int j=7;j>=0;j--){ run += c[j]; hist[base+j]=run; }
    }
    __syncthreads();
    if (tid<256){
      unsigned ge = hist[tid];
      unsigned gt = (tid<255) ? hist[tid+1] : 0u;
      if (ge >= (unsigned)kk && gt < (unsigned)kk){
        s_prefix = pfx | ((unsigned)tid << shift);
        s_k = kk - (int)gt;
      }
    }
    __syncthreads();
  }
  unsigned u = s_prefix;
  unsigned tbits = (u & 0x80000000u) ? (u ^ 0x80000000u) : ~u;
  float thr = __uint_as_float(tbits);

  int srv[4];
  int mycnt = 0;
  #pragma unroll
  for (int j=0;j<4;j++){
    int i = tid*4 + j;
    float v = fv[i];
    int s = -1;
    if (v>0.0f && v>=thr){
      int by=i>>6, bx=i&63;
      int p = pos[i];
      int y=p>>9, x=p&511;
      bool ok = true;
      #pragma unroll
      for (int dby=-1;dby<=1;dby++)
        #pragma unroll
        for (int dbx=-1;dbx<=1;dbx++){
          if (dby==0 && dbx==0) continue;
          int nby=by+dby, nbx=bx+dbx;
          if (nby<0||nby>63||nbx<0||nbx>63) continue;
          int n = nby*64+nbx;
          float nv = fv[n];
          if (nv>v && nv>=thr){
            int np = pos[n];
            int ny=np>>9, nx=np&511;
            if (abs(ny-y)<=2 && abs(nx-x)<=2) ok=false;
          }
        }
      s = ok ? p : -1;
    }
    srv[j]=s;
    mycnt += (s>=0);
  }
  int v = mycnt;
  #pragma unroll
  for (int off=1;off<32;off<<=1){
    int n=__shfl_up_sync(0xffffffffu, v, off);
    if (lane>=off) v+=n;
  }
  if (lane==31) wsum[wid]=v;
  __syncthreads();
  if (wid==0){
    int s=wsum[lane];
    #pragma unroll
    for (int off=1;off<32;off<<=1){
      int n=__shfl_up_sync(0xffffffffu, s, off);
      if (lane>=off) s+=n;
    }
    wsum[lane]=s;
  }
  __syncthreads();
  int offs = (wid ? wsum[wid-1] : 0) + v - mycnt;
  #pragma unroll
  for (int j=0;j<4;j++){
    if (srv[j]>=0){
      if (offs < LCAP) g_list[img*LCAP + offs] = srv[j];
      offs++;
    }
  }
  if (tid==1023){
    int tot = wsum[31];
    g_cnt[img] = tot > LCAP ? LCAP : tot;
  }
}

// ============ K4: warp-per-survivor correction + fused final reduction ============
__global__ __launch_bounds__(1024) void k4(const float* __restrict__ scores,
                                           float* __restrict__ out){
  const int tid = threadIdx.x;
  const int wid = tid>>5, lane = tid&31;
  const int w32 = blockIdx.x*32 + wid;
  const int img = w32 / LCAP;
  const int idx = w32 - img*LCAP;
  __shared__ float wsumf[32];
  __shared__ bool isLast;
  float acc = 0.0f;
  if (idx < g_cnt[img]){
    const int s = g_list[w32];
    const float* sp = scores + (size_t)img*HW*HW;
    float wk[7]; gw7(wk);
    const int y = s>>9, x = s&511;
    #pragma unroll
    for (int t=lane; t<49; t+=32){
      int ky=t/7, kx=t-ky*7;
      int yy = refl512(y+ky-3);
      int xx = refl512(x+kx-3);
      float p = sp[yy*HW+xx];
      float lp = fmaxf(__logf(p), -100.0f);
      float l1 = fmaxf(__logf(1.0f-p), -100.0f);
      acc += wk[ky]*wk[kx]*(lp - l1);
    }
  }
  #pragma unroll
  for (int off=16;off;off>>=1) acc += __shfl_down_sync(0xffffffffu, acc, off);
  if (lane==0) wsumf[wid]=acc;
  __syncthreads();
  if (tid==0){
    double s=0.0;
    for (int i=0;i<32;i++) s += (double)wsumf[i];
    g_pc[blockIdx.x]=s;
    __threadfence();
    unsigned t = atomicAdd(&g_arrive, 1u);
    isLast = (t == (unsigned)(gridDim.x-1));
  }
  __syncthreads();
  if (!isLast) return;

  __shared__ double sb[1024], sr[1024], sx[1024];
  double bsum=0.0, rsum=0.0;
  for (int i=tid;i<NPART;i+=1024){ bsum += g_pb[i]; rsum += g_pr[i]; }
  double csum = (tid<K4CTAS) ? g_pc[tid] : 0.0;
  sb[tid]=bsum; sr[tid]=rsum; sx[tid]=csum;
  __syncthreads();
  for (int s=512;s;s>>=1){
    if (tid<s){ sb[tid]+=sb[tid+s]; sr[tid]+=sr[tid+s]; sx[tid]+=sx[tid+s]; }
    __syncthreads();
  }
  if (tid==0){
    double n = (double)NPIX;
    out[0] = (float)((sb[0]-sx[0])/n + (sr[0]/n)*10.0);
    g_arrive = 0u;
  }
}

// ---------------- launch ----------------
extern "C" void kernel_launch(void* const* d_in, const int* in_sizes, int n_in,
                              void* d_out, int out_size){
  const float* scores = (const float*)d_in[0];
  const float* imgs   = (const float*)d_in[1];
  if (in_sizes[0] != NB*1*HW*HW){
    const float* tmp = scores; scores = imgs; imgs = tmp;
  }
  const int smem_bytes = BUFSZ*4;  // 105216
  static int configured = 0;
  if (!configured){
    cudaFuncSetAttribute(kmain, cudaFuncAttributeMaxDynamicSharedMemorySize, smem_bytes);
    configured = 1;
  }
  dim3 blk(32,32);
  dim3 grd(8,16,NB);
  kmain<<<grd, blk, smem_bytes>>>(imgs, scores);
  k2<<<NB, 1024>>>();
  k4<<<K4CTAS, 1024>>>(scores, (float*)d_out);
}